// round 4
// baseline (speedup 1.0000x reference)
#include <cuda_runtime.h>
#include <cuda_bf16.h>
#include <cstdint>

// StimulusLayer: dist[b,o] = max_i |x[b,i] - stim[o,i]| (Chebyshev),
// out = state*0.95 + sigmoid((a-dist)*b).  B=128, I=256, O=4096.
//
// R3: L1-wavefront relief. lane <-> o mapping: each lane holds its stim
// chunk (8 float4) in registers; x read via uniform broadcast LDS.
// Block 64 thr (2 warps x 32 o), b-tile 4, 2048 blocks.
// stim double-buffered via cp.async, x staged once.

#define B_DIM  128
#define I_DIM  256
#define O_DIM  4096
#define KC     32
#define NCHUNK (I_DIM / KC)        // 8
#define BT     4                   // b rows per block/thread
#define OT     64                  // o per block (2 warps x 32)
#define PITCHS 36                  // stim row pitch (floats): conflict-free spread LDS
#define XPITCH 256                 // x row pitch (floats); broadcast reads, no conflicts

__device__ __forceinline__ void cp_async16(uint32_t saddr, const void* gptr) {
    asm volatile("cp.async.cg.shared.global [%0], [%1], 16;" :: "r"(saddr), "l"(gptr));
}
__device__ __forceinline__ void cp_commit() {
    asm volatile("cp.async.commit_group;");
}

__global__ __launch_bounds__(64)
void stimulus_kernel(const float* __restrict__ x,
                     const float* __restrict__ stim,
                     const float* __restrict__ a,
                     const float* __restrict__ bvec,
                     const float* __restrict__ state,
                     float* __restrict__ out)
{
    __shared__ float xs[BT * XPITCH];            // 4 x 256 floats = 4 KB (all chunks)
    __shared__ float ss[2][OT * PITCHS];         // 2 x 64 x 36 = 18.4 KB

    const int tid  = threadIdx.x;                // 0..63
    const int lane = tid & 31;
    const int wid  = tid >> 5;                   // 0..1
    const int b0   = blockIdx.y * BT;
    const int o0   = blockIdx.x * OT;
    const int orow = wid * 32 + lane;            // this thread's o row within tile

    const float4* __restrict__ x4 = (const float4*)x;
    const float4* __restrict__ s4 = (const float4*)stim;

    const uint32_t xs_base = (uint32_t)__cvta_generic_to_shared(&xs[0]);
    uint32_t ss_base[2];
    ss_base[0] = (uint32_t)__cvta_generic_to_shared(&ss[0][0]);
    ss_base[1] = (uint32_t)__cvta_generic_to_shared(&ss[1][0]);

    // ---- stage x fully (4 rows x 64 f4 = 256 f4, 4 per thread) ----
    #pragma unroll
    for (int t = 0; t < 4; t++) {
        int idx = tid + t * 64;                  // 0..255
        int row = idx >> 6, col = idx & 63;
        cp_async16(xs_base + (row * XPITCH + col * 4) * 4,
                   &x4[(b0 + row) * (I_DIM / 4) + col]);
    }
    // ---- stage stim chunk (64 rows x 8 f4 = 512 f4, 8 per thread) ----
    auto stage_stim = [&](int kc, int buf) {
        #pragma unroll
        for (int t = 0; t < 8; t++) {
            int idx = tid + t * 64;              // 0..511
            int row = idx >> 3, col = idx & 7;
            cp_async16(ss_base[buf] + (row * PITCHS + col * 4) * 4,
                       &s4[(o0 + row) * (I_DIM / 4) + kc * (KC / 4) + col]);
        }
        cp_commit();
    };

    stage_stim(0, 0);
    cp_commit();                                 // (x joins group 0 via first commit above)

    float m[BT];
    #pragma unroll
    for (int jb = 0; jb < BT; jb++) m[jb] = 0.0f;   // |d| >= 0

    #pragma unroll
    for (int kc = 0; kc < NCHUNK; kc++) {
        asm volatile("cp.async.wait_group 0;" ::: "memory");
        __syncthreads();                          // buffer kc ready; other buffer free

        const int buf = kc & 1;
        if (kc + 1 < NCHUNK)
            stage_stim(kc + 1, buf ^ 1);          // overlaps compute of chunk kc

        // lane's stim row -> registers (8 spread LDS.128, conflict-free)
        float4 sreg[KC / 4];
        const float* srow = &ss[buf][orow * PITCHS];
        #pragma unroll
        for (int k4 = 0; k4 < KC / 4; k4++)
            sreg[k4] = *(const float4*)&srow[k4 * 4];

        // x via uniform broadcast LDS, compute against registers
        #pragma unroll
        for (int jb = 0; jb < BT; jb++) {
            const float* xrow = &xs[jb * XPITCH + kc * KC];
            float mm = m[jb];
            #pragma unroll
            for (int k4 = 0; k4 < KC / 4; k4++) {
                float4 xv = *(const float4*)&xrow[k4 * 4];
                mm = fmaxf(mm, fabsf(xv.x - sreg[k4].x));
                mm = fmaxf(mm, fabsf(xv.y - sreg[k4].y));
                mm = fmaxf(mm, fabsf(xv.z - sreg[k4].z));
                mm = fmaxf(mm, fabsf(xv.w - sreg[k4].w));
            }
            m[jb] = mm;
        }
    }

    // ---- epilogue: sigmoid((a - dist) * bvec) + decayed state ----
    const int o  = o0 + orow;
    const float av = a[o];
    const float bv = bvec[o];
    #pragma unroll
    for (int jb = 0; jb < BT; jb++) {
        int b = b0 + jb;
        float z   = (av - m[jb]) * bv;
        float val = 1.0f / (1.0f + __expf(-z));
        long idx  = (long)b * O_DIM + o;
        out[idx]  = state[idx] * 0.95f + val;     // 32 consecutive o -> coalesced
    }
}

extern "C" void kernel_launch(void* const* d_in, const int* in_sizes, int n_in,
                              void* d_out, int out_size)
{
    const float* x     = (const float*)d_in[0];   // (128, 256)
    const float* stim  = (const float*)d_in[1];   // (4096, 256)
    const float* a     = (const float*)d_in[2];   // (4096,)
    const float* bvec  = (const float*)d_in[3];   // (4096,)
    const float* state = (const float*)d_in[4];   // (128, 4096)
    float* out = (float*)d_out;                   // (128, 4096)

    dim3 grid(O_DIM / OT, B_DIM / BT);            // 64 x 32 = 2048 blocks
    stimulus_kernel<<<grid, 64>>>(x, stim, a, bvec, state, out);
}

// round 6
// speedup vs baseline: 1.0215x; 1.0215x over previous
#include <cuda_runtime.h>
#include <cuda_bf16.h>
#include <cstdint>

// StimulusLayer: dist[b,o] = max_i |x[b,i] - stim[o,i]| (Chebyshev),
// out = state*0.95 + sigmoid((a-dist)*b).  B=128, I=256, O=4096.
//
// R5: R2 shape (128 thr, 8b x 64o, thread 2b x 2o, 3-stage cp.async, KC=32)
// + explicit k4-level register double-buffering so LDS results are consumed
// a full iteration after issue (hide 29+ cyc LDS latency).

#define B_DIM 128
#define I_DIM 256
#define O_DIM 4096
#define KC     32
#define PITCHF 36                 // 32 + 4 pad floats; 8-lane phases conflict-free
#define XROWS  8
#define SROWS  64
#define ROWSPB (XROWS + SROWS)
#define NCHUNK (I_DIM / KC)       // 8

__device__ __forceinline__ void cp_async16(uint32_t saddr, const void* gptr) {
    asm volatile("cp.async.cg.shared.global [%0], [%1], 16;" :: "r"(saddr), "l"(gptr));
}
__device__ __forceinline__ void cp_commit() {
    asm volatile("cp.async.commit_group;");
}

__global__ __launch_bounds__(128)
void stimulus_kernel(const float* __restrict__ x,
                     const float* __restrict__ stim,
                     const float* __restrict__ a,
                     const float* __restrict__ bvec,
                     const float* __restrict__ state,
                     float* __restrict__ out)
{
    __shared__ float sb[3][ROWSPB * PITCHF];   // 31104 B

    const int tid = threadIdx.x;          // 0..127
    const int tb  = tid >> 5;             // warp id -> b group (x reads = broadcast)
    const int to  = tid & 31;             // lane -> o (coalesced epilogue)

    const int b0 = blockIdx.y * 8;
    const int o0 = blockIdx.x * 64;

    const float4* __restrict__ x4 = (const float4*)x;
    const float4* __restrict__ s4 = (const float4*)stim;

    uint32_t sb_base[3];
    #pragma unroll
    for (int i = 0; i < 3; i++)
        sb_base[i] = (uint32_t)__cvta_generic_to_shared(&sb[i][0]);

    auto stage = [&](int kc, int buf) {
        if (tid < 64) {                   // x: 8 rows x 8 f4
            int row = tid >> 3, col = tid & 7;
            cp_async16(sb_base[buf] + (row * PITCHF + col * 4) * 4,
                       &x4[(b0 + row) * (I_DIM / 4) + kc * (KC / 4) + col]);
        }
        #pragma unroll
        for (int t = 0; t < 4; t++) {     // stim: 64 rows x 8 f4
            int idx = tid + t * 128;
            int row = idx >> 3, col = idx & 7;
            cp_async16(sb_base[buf] + ((XROWS + row) * PITCHF + col * 4) * 4,
                       &s4[(o0 + row) * (I_DIM / 4) + kc * (KC / 4) + col]);
        }
        cp_commit();
    };

    float m00 = 0.f, m01 = 0.f, m10 = 0.f, m11 = 0.f;   // [jb][jo], |d| >= 0

    stage(0, 0);
    stage(1, 1);

    #pragma unroll
    for (int kc = 0; kc < NCHUNK; kc++) {
        if (kc < NCHUNK - 1) {
            asm volatile("cp.async.wait_group 1;" ::: "memory");
        } else {
            asm volatile("cp.async.wait_group 0;" ::: "memory");
        }
        __syncthreads();

        if (kc + 2 < NCHUNK)
            stage(kc + 2, (kc + 2) % 3);

        const int buf = kc % 3;
        const float* xsb = &sb[buf][0];
        const float* ssb = &sb[buf][XROWS * PITCHF];

        // ---- register double-buffered k4 pipeline ----
        float4 xv[2][2], sv[2][2];        // [pipe][jb/jo]

        xv[0][0] = *(const float4*)&xsb[(tb + 0) * PITCHF + 0];
        xv[0][1] = *(const float4*)&xsb[(tb + 4) * PITCHF + 0];
        sv[0][0] = *(const float4*)&ssb[(to +  0) * PITCHF + 0];
        sv[0][1] = *(const float4*)&ssb[(to + 32) * PITCHF + 0];

        #pragma unroll
        for (int k4 = 0; k4 < KC / 4; k4++) {
            const int cur = k4 & 1, nxt = cur ^ 1;
            if (k4 + 1 < KC / 4) {        // prefetch next k4 into alternate regs
                const int c = (k4 + 1) * 4;
                xv[nxt][0] = *(const float4*)&xsb[(tb + 0) * PITCHF + c];
                xv[nxt][1] = *(const float4*)&xsb[(tb + 4) * PITCHF + c];
                sv[nxt][0] = *(const float4*)&ssb[(to +  0) * PITCHF + c];
                sv[nxt][1] = *(const float4*)&ssb[(to + 32) * PITCHF + c];
            }
            // 4 independent accumulator chains, FADD/FMNMX interleaved
            #define STEP(MM, XV, SV) \
                MM = fmaxf(MM, fabsf((XV).x - (SV).x)); \
                MM = fmaxf(MM, fabsf((XV).y - (SV).y)); \
                MM = fmaxf(MM, fabsf((XV).z - (SV).z)); \
                MM = fmaxf(MM, fabsf((XV).w - (SV).w));
            STEP(m00, xv[cur][0], sv[cur][0])
            STEP(m01, xv[cur][0], sv[cur][1])
            STEP(m10, xv[cur][1], sv[cur][0])
            STEP(m11, xv[cur][1], sv[cur][1])
            #undef STEP
        }
    }

    // ---- epilogue ----
    float m[2][2] = {{m00, m01}, {m10, m11}};
    #pragma unroll
    for (int jo = 0; jo < 2; jo++) {
        int o = o0 + to + 32 * jo;
        float av = a[o];
        float bv = bvec[o];
        #pragma unroll
        for (int jb = 0; jb < 2; jb++) {
            int b = b0 + tb + 4 * jb;
            float z   = (av - m[jb][jo]) * bv;
            float val = 1.0f / (1.0f + __expf(-z));
            long idx  = (long)b * O_DIM + o;
            out[idx]  = state[idx] * 0.95f + val;
        }
    }
}

extern "C" void kernel_launch(void* const* d_in, const int* in_sizes, int n_in,
                              void* d_out, int out_size)
{
    const float* x     = (const float*)d_in[0];   // (128, 256)
    const float* stim  = (const float*)d_in[1];   // (4096, 256)
    const float* a     = (const float*)d_in[2];   // (4096,)
    const float* bvec  = (const float*)d_in[3];   // (4096,)
    const float* state = (const float*)d_in[4];   // (128, 4096)
    float* out = (float*)d_out;                   // (128, 4096)

    dim3 grid(O_DIM / 64, B_DIM / 8);             // 64 x 16 = 1024 blocks
    stimulus_kernel<<<grid, 128>>>(x, stim, a, bvec, state, out);
}

// round 7
// speedup vs baseline: 1.0901x; 1.0672x over previous
#include <cuda_runtime.h>
#include <cuda_bf16.h>
#include <cstdint>

// StimulusLayer: dist[b,o] = max_i |x[b,i] - stim[o,i]| (Chebyshev),
// out = state*0.95 + sigmoid((a-dist)*b).  B=128, I=256, O=4096.
//
// R6: LDG-direct design (no smem mainloop, no barriers).
//  K1: transpose stim -> stimT[k][o] (static __device__ 4MB).
//  K2: warp = 64 o (lane->float2, coalesced stimT LDG) x 8 b (uniform x LDG,
//      L1-resident) x k-split 4. smem only for final 4-way max reduce.

#define B_DIM 128
#define I_DIM 256
#define O_DIM 4096

__device__ float g_stimT[I_DIM * O_DIM];      // [k][o], 4 MB

// ---------------- transpose: stim[o][k] -> stimT[k][o] ----------------
__global__ __launch_bounds__(256)
void transpose_kernel(const float* __restrict__ stim)
{
    __shared__ float tile[32][33];
    const int tx = threadIdx.x;               // 0..31
    const int ty = threadIdx.y;               // 0..7
    const int o0 = blockIdx.x * 32;
    const int k0 = blockIdx.y * 32;

    #pragma unroll
    for (int r = 0; r < 4; r++)
        tile[ty + 8 * r][tx] = stim[(o0 + ty + 8 * r) * I_DIM + k0 + tx];
    __syncthreads();
    #pragma unroll
    for (int r = 0; r < 4; r++)
        g_stimT[(k0 + ty + 8 * r) * O_DIM + o0 + tx] = tile[tx][ty + 8 * r];
}

// ---------------- main kernel ----------------
__global__ __launch_bounds__(128)
void stimulus_kernel(const float* __restrict__ x,
                     const float* __restrict__ a,
                     const float* __restrict__ bvec,
                     const float* __restrict__ state,
                     float* __restrict__ out)
{
    __shared__ float2 part[4][8][32];         // [ksplit][jb][o-pair] = 8 KB

    const int tid  = threadIdx.x;             // 0..127
    const int w    = tid >> 5;                // k-split 0..3
    const int lane = tid & 31;

    const int b0 = blockIdx.y * 8;
    const int o0 = blockIdx.x * 64;
    const int kbase = w * 64;                 // 64 k per warp = 16 k4 iters

    const float4* __restrict__ x4  = (const float4*)x;            // row = 64 f4
    const float2* __restrict__ sT2 = (const float2*)g_stimT;      // row = 2048 f2

    const int sidx = o0 / 2 + lane;           // float2 col in stimT row

    float2 acc[8];
    #pragma unroll
    for (int jb = 0; jb < 8; jb++) acc[jb] = make_float2(0.f, 0.f);

    #pragma unroll 4
    for (int k4 = 0; k4 < 16; k4++) {
        const int k = kbase + k4 * 4;

        float4 xv[8];                         // uniform, L1-hit (x = 128 KB)
        #pragma unroll
        for (int jb = 0; jb < 8; jb++)
            xv[jb] = x4[(b0 + jb) * (I_DIM / 4) + (k >> 2)];

        float2 sv[4];                         // coalesced 256B per k
        #pragma unroll
        for (int j = 0; j < 4; j++)
            sv[j] = sT2[(k + j) * (O_DIM / 2) + sidx];

        #pragma unroll
        for (int j = 0; j < 4; j++) {
            #pragma unroll
            for (int jb = 0; jb < 8; jb++) {
                const float xs = (j == 0) ? xv[jb].x :
                                 (j == 1) ? xv[jb].y :
                                 (j == 2) ? xv[jb].z : xv[jb].w;
                acc[jb].x = fmaxf(acc[jb].x, fabsf(xs - sv[j].x));
                acc[jb].y = fmaxf(acc[jb].y, fabsf(xs - sv[j].y));
            }
        }
    }

    // write partials (conflict-free STS.64)
    #pragma unroll
    for (int jb = 0; jb < 8; jb++)
        part[w][jb][lane] = acc[jb];
    __syncthreads();

    // reduce 4 k-splits + epilogue: thread t -> 4 consecutive o, one b row
    const int jb  = tid >> 4;                 // 0..7
    const int lp  = (tid & 15) * 2;           // float2-pair index 0..30
    const int oc  = blockIdx.x * 16 + (tid & 15);   // float4 col in o

    float4 m0 = *(const float4*)&part[0][jb][lp];
    float4 m1 = *(const float4*)&part[1][jb][lp];
    float4 m2 = *(const float4*)&part[2][jb][lp];
    float4 m3 = *(const float4*)&part[3][jb][lp];
    float4 mx;
    mx.x = fmaxf(fmaxf(m0.x, m1.x), fmaxf(m2.x, m3.x));
    mx.y = fmaxf(fmaxf(m0.y, m1.y), fmaxf(m2.y, m3.y));
    mx.z = fmaxf(fmaxf(m0.z, m1.z), fmaxf(m2.z, m3.z));
    mx.w = fmaxf(fmaxf(m0.w, m1.w), fmaxf(m2.w, m3.w));

    const float4* __restrict__ a4 = (const float4*)a;
    const float4* __restrict__ b4 = (const float4*)bvec;
    const float4* __restrict__ s4 = (const float4*)state;
    float4*       __restrict__ o4 = (float4*)out;

    const float4 av = a4[oc];
    const float4 bv = b4[oc];
    const int    bg = b0 + jb;
    const float4 st = s4[bg * (O_DIM / 4) + oc];

    float4 r;
    r.x = st.x * 0.95f + 1.0f / (1.0f + __expf(-(av.x - mx.x) * bv.x));
    r.y = st.y * 0.95f + 1.0f / (1.0f + __expf(-(av.y - mx.y) * bv.y));
    r.z = st.z * 0.95f + 1.0f / (1.0f + __expf(-(av.z - mx.z) * bv.z));
    r.w = st.w * 0.95f + 1.0f / (1.0f + __expf(-(av.w - mx.w) * bv.w));
    o4[bg * (O_DIM / 4) + oc] = r;
}

extern "C" void kernel_launch(void* const* d_in, const int* in_sizes, int n_in,
                              void* d_out, int out_size)
{
    const float* x     = (const float*)d_in[0];   // (128, 256)
    const float* stim  = (const float*)d_in[1];   // (4096, 256)
    const float* a     = (const float*)d_in[2];   // (4096,)
    const float* bvec  = (const float*)d_in[3];   // (4096,)
    const float* state = (const float*)d_in[4];   // (128, 4096)
    float* out = (float*)d_out;                   // (128, 4096)

    dim3 tgrid(O_DIM / 32, I_DIM / 32);           // 128 x 8
    transpose_kernel<<<tgrid, dim3(32, 8)>>>(stim);

    dim3 grid(O_DIM / 64, B_DIM / 8);             // 64 x 16 = 1024 blocks
    stimulus_kernel<<<grid, 128>>>(x, a, bvec, state, out);
}